// round 4
// baseline (speedup 1.0000x reference)
#include <cuda_runtime.h>
#include <cuda_bf16.h>
#include <cstdint>

// Problem constants (fixed by dataset)
#define B_DIM   2048
#define IN_DIM  1024
#define H_DIM   2048
#define OUT_DIM 1024
#define BSB     32
#define RBX     64
#define NNZ     (64 * 32)

// ---------------------------------------------------------------------------
// Pre-split bf16 hi/lo device globals (no allocation allowed)
// ---------------------------------------------------------------------------
__device__ __nv_bfloat16 g_xhi[(size_t)B_DIM * IN_DIM],  g_xlo[(size_t)B_DIM * IN_DIM];
__device__ __nv_bfloat16 g_w1hi[(size_t)H_DIM * IN_DIM], g_w1lo[(size_t)H_DIM * IN_DIM];
__device__ __nv_bfloat16 g_w3hi[(size_t)OUT_DIM * H_DIM],g_w3lo[(size_t)OUT_DIM * H_DIM];
__device__ __nv_bfloat16 g_vhi[(size_t)NNZ * BSB * BSB], g_vlo[(size_t)NNZ * BSB * BSB];
__device__ __nv_bfloat16 g_h1hi[(size_t)B_DIM * H_DIM],  g_h1lo[(size_t)B_DIM * H_DIM];
__device__ __nv_bfloat16 g_h2hi[(size_t)B_DIM * H_DIM],  g_h2lo[(size_t)B_DIM * H_DIM];

// ---------------------------------------------------------------------------
// Helpers
// ---------------------------------------------------------------------------
__device__ __forceinline__ uint32_t smem_u32(const void* p) {
    uint32_t a;
    asm("{ .reg .u64 t; cvta.to.shared.u64 t, %1; cvt.u32.u64 %0, t; }"
        : "=r"(a) : "l"(p));
    return a;
}

__device__ __forceinline__ void cp16(uint32_t dst, const void* src) {
    asm volatile("cp.async.cg.shared.global [%0], [%1], 16;"
                 :: "r"(dst), "l"(src) : "memory");
}
#define CP_COMMIT() asm volatile("cp.async.commit_group;" ::: "memory")
#define CP_WAIT(N)  asm volatile("cp.async.wait_group %0;" :: "n"(N) : "memory")

__device__ __forceinline__ void ldsm_x4(uint32_t (&r)[4], uint32_t addr) {
    asm volatile("ldmatrix.sync.aligned.m8n8.x4.shared.b16 {%0,%1,%2,%3}, [%4];"
                 : "=r"(r[0]), "=r"(r[1]), "=r"(r[2]), "=r"(r[3]) : "r"(addr));
}

__device__ __forceinline__ void mma_bf16(float c[4], const uint32_t a[4],
                                         const uint32_t b[2]) {
    asm volatile(
        "mma.sync.aligned.m16n8k16.row.col.f32.bf16.bf16.f32 "
        "{%0,%1,%2,%3}, {%4,%5,%6,%7}, {%8,%9}, {%0,%1,%2,%3};"
        : "+f"(c[0]), "+f"(c[1]), "+f"(c[2]), "+f"(c[3])
        : "r"(a[0]), "r"(a[1]), "r"(a[2]), "r"(a[3]), "r"(b[0]), "r"(b[1]));
}

// Split a float into bf16 hi + residual lo
__device__ __forceinline__ void split1(float v, __nv_bfloat16& h, __nv_bfloat16& l) {
    h = __float2bfloat16_rn(v);
    l = __float2bfloat16_rn(v - __bfloat162float(h));
}

// ---------------------------------------------------------------------------
// Split kernel: fp32 -> bf16 hi/lo, 4 floats per thread
// ---------------------------------------------------------------------------
__global__ __launch_bounds__(256) void split_kernel(
    const float4* __restrict__ src, uint2* __restrict__ hi,
    uint2* __restrict__ lo, int n4)
{
    const int i = blockIdx.x * 256 + threadIdx.x;
    if (i >= n4) return;
    float4 v = src[i];
    __nv_bfloat162 h0 = __floats2bfloat162_rn(v.x, v.y);
    __nv_bfloat162 h1 = __floats2bfloat162_rn(v.z, v.w);
    float2 f0 = __bfloat1622float2(h0);
    float2 f1 = __bfloat1622float2(h1);
    __nv_bfloat162 l0 = __floats2bfloat162_rn(v.x - f0.x, v.y - f0.y);
    __nv_bfloat162 l1 = __floats2bfloat162_rn(v.z - f1.x, v.w - f1.y);
    uint2 hw; hw.x = *(uint32_t*)&h0; hw.y = *(uint32_t*)&h1;
    uint2 lw; lw.x = *(uint32_t*)&l0; lw.y = *(uint32_t*)&l1;
    hi[i] = hw;
    lo[i] = lw;
}

// ---------------------------------------------------------------------------
// Dense GEMM (NT): C = act(A @ B^T + bias). A,B pre-split bf16 hi/lo.
// CTA 128x128, 8 warps (64x32 warp tiles), K-chunk 32.
// 4-stage cp.async pipeline; ldmatrix fragments.
// smem row stride 80B (16B-pad) -> conflict-free cp.async + ldmatrix.
// MODE 0: fp32 out + bias.  MODE 1: relu, write bf16 hi/lo arrays.
// ---------------------------------------------------------------------------
#define ROWB   80
#define ATILE  (128 * ROWB)       // 10240 B
#define DSTG   (4 * ATILE)        // 40960 B per stage
#define DS     4
#define D_SMEM (DS * DSTG)        // 163840 B

template <int MODE>
__global__ __launch_bounds__(256, 1) void gemm_cp_kernel(
    const __nv_bfloat16* __restrict__ Ahi, const __nv_bfloat16* __restrict__ Alo,
    const __nv_bfloat16* __restrict__ Bhi, const __nv_bfloat16* __restrict__ Blo,
    const float* __restrict__ bias, float* __restrict__ Cf,
    __nv_bfloat16* __restrict__ Chi, __nv_bfloat16* __restrict__ Clo,
    int N, int K)
{
    extern __shared__ char sm[];
    const uint32_t sb = smem_u32(sm);
    const int tid  = threadIdx.x;
    const int lane = tid & 31;
    const int wid  = tid >> 5;
    const int brow = blockIdx.y * 128;
    const int bcol = blockIdx.x * 128;
    const int wm = (wid >> 2) * 64;
    const int wn = (wid & 3) * 32;
    const int chunks = K / 32;

    float acc[4][4][4];
#pragma unroll
    for (int i = 0; i < 4; i++)
#pragma unroll
        for (int j = 0; j < 4; j++)
#pragma unroll
            for (int r = 0; r < 4; r++) acc[i][j][r] = 0.0f;

    // cp.async mapping: 512 segs of 16B per tile; thread handles segs tid, tid+256
    auto issue = [&](int ki) {
        const int k0 = ki * 32;
        const uint32_t bufo = sb + (uint32_t)(ki & (DS - 1)) * DSTG;
#pragma unroll
        for (int t = 0; t < 2; t++) {
            const int seg = tid + t * 256;
            const int row = seg >> 2, s = seg & 3;
            const uint32_t d = bufo + row * ROWB + s * 16;
            const size_t ga = (size_t)(brow + row) * K + k0 + s * 8;
            cp16(d,             Ahi + ga);
            cp16(d + ATILE,     Alo + ga);
            const size_t gb = (size_t)(bcol + row) * K + k0 + s * 8;
            cp16(d + 2 * ATILE, Bhi + gb);
            cp16(d + 3 * ATILE, Blo + gb);
        }
    };

    // prologue: stages 0..DS-2
#pragma unroll
    for (int s = 0; s < DS - 1; s++) {
        if (s < chunks) issue(s);
        CP_COMMIT();
    }

    // fragment smem address components (per thread)
    const uint32_t aoff = (wm + (lane & 15)) * ROWB + ((lane >> 4) & 1) * 16;
    const uint32_t boff = (wn + ((lane >> 4) & 1) * 8 + (lane & 7)) * ROWB +
                          ((lane >> 3) & 1) * 16;

    for (int kc = 0; kc < chunks; kc++) {
        const int ki = kc + DS - 1;
        if (ki < chunks) { issue(ki); CP_COMMIT(); CP_WAIT(DS - 1); }
        else             { CP_COMMIT(); CP_WAIT(0); }
        __syncthreads();

        const uint32_t base = sb + (uint32_t)(kc & (DS - 1)) * DSTG;
#pragma unroll
        for (int ks = 0; ks < 2; ks++) {
            uint32_t ah[4][4], al[4][4], bh[2][4], bl[2][4];
#pragma unroll
            for (int i = 0; i < 4; i++)
                ldsm_x4(ah[i], base + aoff + i * (16 * ROWB) + ks * 32);
#pragma unroll
            for (int i = 0; i < 4; i++)
                ldsm_x4(al[i], base + ATILE + aoff + i * (16 * ROWB) + ks * 32);
#pragma unroll
            for (int jp = 0; jp < 2; jp++)
                ldsm_x4(bh[jp], base + 2 * ATILE + boff + jp * (16 * ROWB) + ks * 32);
#pragma unroll
            for (int jp = 0; jp < 2; jp++)
                ldsm_x4(bl[jp], base + 3 * ATILE + boff + jp * (16 * ROWB) + ks * 32);
#pragma unroll
            for (int i = 0; i < 4; i++)
#pragma unroll
                for (int j = 0; j < 4; j++) {
                    const uint32_t* bhp = &bh[j >> 1][(j & 1) * 2];
                    const uint32_t* blp = &bl[j >> 1][(j & 1) * 2];
                    mma_bf16(acc[i][j], ah[i], bhp);
                    mma_bf16(acc[i][j], ah[i], blp);
                    mma_bf16(acc[i][j], al[i], bhp);
                }
        }
        __syncthreads();
    }

    // epilogue
#pragma unroll
    for (int i = 0; i < 4; i++) {
        const int r0 = brow + wm + i * 16 + (lane >> 2);
#pragma unroll
        for (int j = 0; j < 4; j++) {
            const int c0 = bcol + wn + j * 8 + 2 * (lane & 3);
            const float bx = __ldg(&bias[c0]), by = __ldg(&bias[c0 + 1]);
            float v00 = acc[i][j][0] + bx, v01 = acc[i][j][1] + by;
            float v10 = acc[i][j][2] + bx, v11 = acc[i][j][3] + by;
            if (MODE == 0) {
                *(float2*)(Cf + (size_t)r0 * N + c0)       = make_float2(v00, v01);
                *(float2*)(Cf + (size_t)(r0 + 8) * N + c0) = make_float2(v10, v11);
            } else {
                v00 = fmaxf(v00, 0.f); v01 = fmaxf(v01, 0.f);
                v10 = fmaxf(v10, 0.f); v11 = fmaxf(v11, 0.f);
                __nv_bfloat16 h0, l0, h1, l1;
                split1(v00, h0, l0); split1(v01, h1, l1);
                *(__nv_bfloat162*)(Chi + (size_t)r0 * N + c0) = __nv_bfloat162(h0, h1);
                *(__nv_bfloat162*)(Clo + (size_t)r0 * N + c0) = __nv_bfloat162(l0, l1);
                split1(v10, h0, l0); split1(v11, h1, l1);
                *(__nv_bfloat162*)(Chi + (size_t)(r0 + 8) * N + c0) = __nv_bfloat162(h0, h1);
                *(__nv_bfloat162*)(Clo + (size_t)(r0 + 8) * N + c0) = __nv_bfloat162(l0, l1);
            }
        }
    }
}

// ---------------------------------------------------------------------------
// BSR layer: per (batch-tile 128, row-block rb):
//   h2[., rb*32:+32] = relu( sum_p h1[., col_p*32:+32] @ vals[p]^T + b2 )
// 8 warps (32x16 warp tiles). 4-stage cp.async. bf16 hi/lo in and out.
// ---------------------------------------------------------------------------
#define SB_HI  (2 * ATILE)            // Bhi offset: 20480
#define SB_LO  (2 * ATILE + 2560)     // Blo offset: 23040
#define SSTG   (2 * ATILE + 2 * 2560) // 25600 B per stage
#define SS     4
#define S_SMEM (SS * SSTG)            // 102400 B

__global__ __launch_bounds__(256, 2) void bsr_cp_kernel(
    const __nv_bfloat16* __restrict__ h1hi, const __nv_bfloat16* __restrict__ h1lo,
    const int* __restrict__ crow, const int* __restrict__ cols,
    const __nv_bfloat16* __restrict__ vhi, const __nv_bfloat16* __restrict__ vlo,
    const float* __restrict__ bias,
    __nv_bfloat16* __restrict__ h2hi, __nv_bfloat16* __restrict__ h2lo)
{
    extern __shared__ char sm[];
    const uint32_t sb = smem_u32(sm);
    const int tid  = threadIdx.x;
    const int lane = tid & 31;
    const int wid  = tid >> 5;
    const int b0 = blockIdx.x * 128;
    const int rb = blockIdx.y;
    const int wm = (wid >> 1) * 32;
    const int wn = (wid & 1) * 16;

    float acc[2][2][4];
#pragma unroll
    for (int i = 0; i < 2; i++)
#pragma unroll
        for (int j = 0; j < 2; j++)
#pragma unroll
            for (int r = 0; r < 4; r++) acc[i][j][r] = 0.0f;

    const int s0 = __ldg(&crow[rb]);
    const int chunks = __ldg(&crow[rb + 1]) - s0;

    auto issue = [&](int ki) {
        const int p = s0 + ki;
        const int cb = __ldg(&cols[p]);
        const uint32_t bufo = sb + (uint32_t)(ki & (SS - 1)) * SSTG;
#pragma unroll
        for (int t = 0; t < 2; t++) {
            const int seg = tid + t * 256;
            const int row = seg >> 2, s = seg & 3;
            const uint32_t d = bufo + row * ROWB + s * 16;
            const size_t ga = (size_t)(b0 + row) * H_DIM + cb * 32 + s * 8;
            cp16(d,         h1hi + ga);
            cp16(d + ATILE, h1lo + ga);
        }
        // B: 128 segs, threads 0-127 -> hi, 128-255 -> lo
        const int seg = tid & 127;
        const int row = seg >> 2, s = seg & 3;
        const uint32_t d = bufo + (tid < 128 ? SB_HI : SB_LO) + row * ROWB + s * 16;
        const __nv_bfloat16* src = (tid < 128 ? vhi : vlo) +
                                   (size_t)p * (BSB * BSB) + row * BSB + s * 8;
        cp16(d, src);
    };

#pragma unroll
    for (int s = 0; s < SS - 1; s++) {
        if (s < chunks) issue(s);
        CP_COMMIT();
    }

    const uint32_t aoff = (wm + (lane & 15)) * ROWB + ((lane >> 4) & 1) * 16;
    const uint32_t boff = (wn + ((lane >> 4) & 1) * 8 + (lane & 7)) * ROWB +
                          ((lane >> 3) & 1) * 16;

    for (int kc = 0; kc < chunks; kc++) {
        const int ki = kc + SS - 1;
        if (ki < chunks) { issue(ki); CP_COMMIT(); CP_WAIT(SS - 1); }
        else             { CP_COMMIT(); CP_WAIT(0); }
        __syncthreads();

        const uint32_t base = sb + (uint32_t)(kc & (SS - 1)) * SSTG;
#pragma unroll
        for (int ks = 0; ks < 2; ks++) {
            uint32_t ah[2][4], al[2][4], bh[4], bl[4];
#pragma unroll
            for (int i = 0; i < 2; i++) {
                ldsm_x4(ah[i], base + aoff + i * (16 * ROWB) + ks * 32);
                ldsm_x4(al[i], base + ATILE + aoff + i * (16 * ROWB) + ks * 32);
            }
            ldsm_x4(bh, base + SB_HI + boff + ks * 32);
            ldsm_x4(bl, base + SB_LO + boff + ks * 32);
#pragma unroll
            for (int i = 0; i < 2; i++)
#pragma unroll
                for (int j = 0; j < 2; j++) {
                    const uint32_t* bhp = &bh[j * 2];
                    const uint32_t* blp = &bl[j * 2];
                    mma_bf16(acc[i][j], ah[i], bhp);
                    mma_bf16(acc[i][j], ah[i], blp);
                    mma_bf16(acc[i][j], al[i], bhp);
                }
        }
        __syncthreads();
    }

    // epilogue: bias + relu -> bf16 hi/lo
#pragma unroll
    for (int i = 0; i < 2; i++) {
        const int r0 = b0 + wm + i * 16 + (lane >> 2);
#pragma unroll
        for (int j = 0; j < 2; j++) {
            const int c0 = rb * 32 + wn + j * 8 + 2 * (lane & 3);
            const float bx = __ldg(&bias[c0]), by = __ldg(&bias[c0 + 1]);
            float v00 = fmaxf(acc[i][j][0] + bx, 0.f);
            float v01 = fmaxf(acc[i][j][1] + by, 0.f);
            float v10 = fmaxf(acc[i][j][2] + bx, 0.f);
            float v11 = fmaxf(acc[i][j][3] + by, 0.f);
            __nv_bfloat16 h0, l0, h1, l1;
            split1(v00, h0, l0); split1(v01, h1, l1);
            *(__nv_bfloat162*)(h2hi + (size_t)r0 * H_DIM + c0) = __nv_bfloat162(h0, h1);
            *(__nv_bfloat162*)(h2lo + (size_t)r0 * H_DIM + c0) = __nv_bfloat162(l0, l1);
            split1(v10, h0, l0); split1(v11, h1, l1);
            *(__nv_bfloat162*)(h2hi + (size_t)(r0 + 8) * H_DIM + c0) = __nv_bfloat162(h0, h1);
            *(__nv_bfloat162*)(h2lo + (size_t)(r0 + 8) * H_DIM + c0) = __nv_bfloat162(l0, l1);
        }
    }
}

// ---------------------------------------------------------------------------
// Launcher
// ---------------------------------------------------------------------------
extern "C" void kernel_launch(void* const* d_in, const int* in_sizes, int n_in,
                              void* d_out, int out_size)
{
    const float* x    = (const float*)d_in[0];
    const float* W1   = (const float*)d_in[1];
    const float* b1   = (const float*)d_in[2];
    const int*   crow = (const int*)d_in[3];
    const int*   cols = (const int*)d_in[4];
    const float* vals = (const float*)d_in[5];
    const float* b2   = (const float*)d_in[6];
    const float* W3   = (const float*)d_in[7];
    const float* b3   = (const float*)d_in[8];
    float* out = (float*)d_out;

    __nv_bfloat16 *xhi, *xlo, *w1hi, *w1lo, *w3hi, *w3lo, *vhi, *vlo;
    __nv_bfloat16 *h1hi, *h1lo, *h2hi, *h2lo;
    cudaGetSymbolAddress((void**)&xhi,  g_xhi);  cudaGetSymbolAddress((void**)&xlo,  g_xlo);
    cudaGetSymbolAddress((void**)&w1hi, g_w1hi); cudaGetSymbolAddress((void**)&w1lo, g_w1lo);
    cudaGetSymbolAddress((void**)&w3hi, g_w3hi); cudaGetSymbolAddress((void**)&w3lo, g_w3lo);
    cudaGetSymbolAddress((void**)&vhi,  g_vhi);  cudaGetSymbolAddress((void**)&vlo,  g_vlo);
    cudaGetSymbolAddress((void**)&h1hi, g_h1hi); cudaGetSymbolAddress((void**)&h1lo, g_h1lo);
    cudaGetSymbolAddress((void**)&h2hi, g_h2hi); cudaGetSymbolAddress((void**)&h2lo, g_h2lo);

    cudaFuncSetAttribute(gemm_cp_kernel<0>,
                         cudaFuncAttributeMaxDynamicSharedMemorySize, D_SMEM);
    cudaFuncSetAttribute(gemm_cp_kernel<1>,
                         cudaFuncAttributeMaxDynamicSharedMemorySize, D_SMEM);
    cudaFuncSetAttribute(bsr_cp_kernel,
                         cudaFuncAttributeMaxDynamicSharedMemorySize, S_SMEM);

    // Pre-split inputs to bf16 hi/lo (each 2M elements -> 512K float4)
    const int n4 = (B_DIM * IN_DIM) / 4;   // same count for x, W1, W3, vals
    split_kernel<<<n4 / 256, 256>>>((const float4*)x,    (uint2*)xhi,  (uint2*)xlo,  n4);
    split_kernel<<<n4 / 256, 256>>>((const float4*)W1,   (uint2*)w1hi, (uint2*)w1lo, n4);
    split_kernel<<<n4 / 256, 256>>>((const float4*)W3,   (uint2*)w3hi, (uint2*)w3lo, n4);
    split_kernel<<<n4 / 256, 256>>>((const float4*)vals, (uint2*)vhi,  (uint2*)vlo,  n4);

    // Layer 1: h1 = relu(x @ W1^T + b1) -> bf16 hi/lo
    gemm_cp_kernel<1><<<dim3(H_DIM / 128, B_DIM / 128), 256, D_SMEM>>>(
        xhi, xlo, w1hi, w1lo, b1, nullptr, h1hi, h1lo, H_DIM, IN_DIM);

    // Layer 2: h2 = relu(BSR(h1) + b2) -> bf16 hi/lo
    bsr_cp_kernel<<<dim3(B_DIM / 128, RBX), 256, S_SMEM>>>(
        h1hi, h1lo, crow, cols, vhi, vlo, b2, h2hi, h2lo);

    // Layer 3: out = h2 @ W3^T + b3 (fp32)
    gemm_cp_kernel<0><<<dim3(OUT_DIM / 128, B_DIM / 128), 256, D_SMEM>>>(
        h2hi, h2lo, w3hi, w3lo, b3, out, nullptr, nullptr, OUT_DIM, H_DIM);
}